// round 14
// baseline (speedup 1.0000x reference)
#include <cuda_runtime.h>
#include <cuda_fp16.h>
#include <math.h>
#include <stdint.h>

#define BB 8
#define HH 256
#define WW 256
#define EE 8192
#define HWSZ 65536
typedef unsigned long long u64;
typedef uint32_t u32;

__device__ __half g_qh[64*64*EE];
__device__ __half g_kh[64*64*EE];
__device__ __half g_vh[64*64*EE];
__device__ float  g_Sp[16*64*4096];
__device__ __half g_P[64*4096];
__device__ __half g_yh[BB*64*HWSZ];
__device__ float  g_x1[BB*64*HWSZ];
__device__ __half g_x1h[BB*64*HWSZ];
__device__ __half g_th[BB*64*HWSZ];
__device__ __half g_wqkvh[192*72];
__device__ float  g_bqkv[192];
__device__ __half g_wth[3*9*64*72];    // [conv][tap][oc][ci] stride 72

__device__ __forceinline__ int refl(int i, int n){
    if (i < 0) i = -i; if (i >= n) i = 2*n-2-i; return i; }
__device__ __forceinline__ float lrelu(float v){ return v > 0.f ? v : 0.2f*v; }

__device__ __forceinline__ void mma16(float* c, u32 a0, u32 a1, u32 a2, u32 a3,
                                      u32 b0, u32 b1){
    asm("mma.sync.aligned.m16n8k16.row.col.f32.f16.f16.f32 "
        "{%0,%1,%2,%3},{%4,%5,%6,%7},{%8,%9},{%0,%1,%2,%3};"
        : "+f"(c[0]),"+f"(c[1]),"+f"(c[2]),"+f"(c[3])
        : "r"(a0),"r"(a1),"r"(a2),"r"(a3),"r"(b0),"r"(b1));
}
__device__ __forceinline__ void ldsm4(u32& r0, u32& r1, u32& r2, u32& r3, u32 addr){
    asm volatile("ldmatrix.sync.aligned.m8n8.x4.shared.b16 {%0,%1,%2,%3}, [%4];"
        : "=r"(r0),"=r"(r1),"=r"(r2),"=r"(r3) : "r"(addr));
}

// ---------- weight transform ----------
__global__ void xform_kernel(const float* __restrict__ wq, const float* __restrict__ bq,
                             const float* __restrict__ wk, const float* __restrict__ bk,
                             const float* __restrict__ wv, const float* __restrict__ bv,
                             const float* __restrict__ wo, const float* __restrict__ wf1,
                             const float* __restrict__ wf2){
    int idx = blockIdx.x*256 + threadIdx.x;
    if (idx < 12288){
        int oc = idx>>6, ci = idx&63;
        int t3 = oc>>6, r = (oc&63)*64 + ci;
        float v = (t3==0) ? wq[r] : (t3==1 ? wk[r] : wv[r]);
        g_wqkvh[oc*72 + ci] = __float2half_rn(v);
    }
    if (idx < 192)
        g_bqkv[idx] = (idx<64) ? bq[idx] : (idx<128 ? bk[idx-64] : bv[idx-128]);
    if (idx < 36864){
        int tap = idx>>12, oc = (idx&4095)>>6, ci = idx&63;
        int s = (oc*64+ci)*9 + tap;
        int d = (tap*64 + oc)*72 + ci;
        g_wth[d]            = __float2half_rn(wo[s]);
        g_wth[41472 + d]    = __float2half_rn(wf1[s]);
        g_wth[2*41472 + d]  = __float2half_rn(wf2[s]);
    }
}

// ---------- qkv 1x1 conv: M=oc192, N=px128, K=ci64 ----------
__global__ __launch_bounds__(256) void qkv_kernel(const float* __restrict__ x){
    extern __shared__ __half smh[];
    __half* Ws = smh;            // [192][72]
    __half* Xn = smh + 13824;    // [128px][72]
    u32* Wsw = (u32*)Ws; u32* Xnw = (u32*)Xn;
    const int tid = threadIdx.x, w = tid>>5, gid = (tid&31)>>2, tig = tid&3;
    const int b = blockIdx.z, y = blockIdx.y, x0 = blockIdx.x*128;
    const u32* gww = (const u32*)g_wqkvh;
    for (int i = tid; i < 6912; i += 256) Wsw[i] = gww[i];
    for (int i = tid; i < 8192; i += 256){
        int ci = i>>7, px = i&127;
        Xn[px*72 + ci] = __float2half_rn(x[(b*64+ci)*HWSZ + y*256 + x0 + px]);
    }
    __syncthreads();
    const int mg = (w&3)*3, nb = (w>>2)*64;
    float acc[3][8][4] = {};
    #pragma unroll
    for (int kc = 0; kc < 4; kc++){
        const int kb = kc*8 + tig;
        u32 bf0[8], bf1[8];
        #pragma unroll
        for (int nt = 0; nt < 8; nt++){
            int px = nb + nt*8 + gid;
            bf0[nt] = Xnw[px*36 + kb];
            bf1[nt] = Xnw[px*36 + kb + 4];
        }
        #pragma unroll
        for (int mt = 0; mt < 3; mt++){
            int oc = (mg+mt)*16 + gid;
            u32 a0 = Wsw[oc*36 + kb],       a1 = Wsw[(oc+8)*36 + kb];
            u32 a2 = Wsw[oc*36 + kb + 4],   a3 = Wsw[(oc+8)*36 + kb + 4];
            #pragma unroll
            for (int nt = 0; nt < 8; nt++)
                mma16(acc[mt][nt], a0, a1, a2, a3, bf0[nt], bf1[nt]);
        }
    }
    const int pyo = (y&31)*32, wrow = (y>>5)*8;
    #pragma unroll
    for (int mt = 0; mt < 3; mt++){
        int ocA = (mg+mt)*16 + gid, ocB = ocA + 8;
        float bA = g_bqkv[ocA], bB = g_bqkv[ocB];
        int t3A = ocA>>6, cA = ocA&63;
        int t3B = ocB>>6, cB = ocB&63;
        __half* pA = (t3A==0?g_qh:(t3A==1?g_kh:g_vh)) + (u64)(b*8+(cA>>3))*64*EE + (cA&7)*1024;
        __half* pB = (t3B==0?g_qh:(t3B==1?g_kh:g_vh)) + (u64)(b*8+(cB>>3))*64*EE + (cB&7)*1024;
        #pragma unroll
        for (int nt = 0; nt < 8; nt++){
            int px = x0 + nb + nt*8 + tig*2;
            int wo2 = (wrow + (px>>5))*EE + pyo + (px&31);
            *(__half2*)&pA[wo2] = __halves2half2(__float2half_rn(acc[mt][nt][0]+bA),
                                                 __float2half_rn(acc[mt][nt][1]+bA));
            *(__half2*)&pB[wo2] = __halves2half2(__float2half_rn(acc[mt][nt][2]+bB),
                                                 __float2half_rn(acc[mt][nt][3]+bB));
        }
    }
}

// ---------- scores ----------
__global__ __launch_bounds__(128) void attn_scores_kernel(){
    __shared__ __half Qs[64*72];
    __shared__ __half Ks[64*72];
    u32* Qsw = (u32*)Qs; u32* Ksw = (u32*)Ks;
    const int bh = blockIdx.x>>4, sl = blockIdx.x&15, e0 = sl*512;
    const int tid = threadIdx.x, w = tid>>5, gid = (tid&31)>>2, tig = tid&3;
    const u32* Qg = (const u32*)g_qh + (u64)bh*64*4096;
    const u32* Kg = (const u32*)g_kh + (u64)bh*64*4096;
    float acc[8][4] = {};
    for (int ec = 0; ec < 8; ec++){
        __syncthreads();
        const int eoff = (e0 + ec*64)>>1;
        for (int i = tid; i < 2048; i += 128){
            int q = i>>5, ew = i&31;
            Qsw[q*36+ew] = Qg[q*4096 + eoff + ew];
            Ksw[q*36+ew] = Kg[q*4096 + eoff + ew];
        }
        __syncthreads();
        #pragma unroll
        for (int kc = 0; kc < 4; kc++){
            const int kb = kc*8 + tig;
            int qr = w*16 + gid;
            u32 a0 = Qsw[qr*36 + kb],     a1 = Qsw[(qr+8)*36 + kb];
            u32 a2 = Qsw[qr*36 + kb + 4], a3 = Qsw[(qr+8)*36 + kb + 4];
            #pragma unroll
            for (int nt = 0; nt < 8; nt++){
                int key = nt*8 + gid;
                mma16(acc[nt], a0, a1, a2, a3, Ksw[key*36+kb], Ksw[key*36+kb+4]);
            }
        }
    }
    float* Sp = g_Sp + (u64)(sl*64+bh)*4096;
    int qA = w*16+gid, qB = qA+8;
    #pragma unroll
    for (int nt = 0; nt < 8; nt++){
        int key = nt*8 + tig*2;
        *(float2*)&Sp[qA*64+key] = make_float2(acc[nt][0], acc[nt][1]);
        *(float2*)&Sp[qB*64+key] = make_float2(acc[nt][2], acc[nt][3]);
    }
}

// ---------- softmax ----------
__global__ void softmax_kernel(){
    const int r = blockIdx.x*8 + (threadIdx.x>>5);
    const int bh = r>>6, q = r&63, lane = threadIdx.x&31;
    const float scale = 0.011048543456039806f;
    float s0 = 0.f, s1 = 0.f;
    #pragma unroll
    for (int sl = 0; sl < 16; sl++){
        const float* p = g_Sp + (u64)(sl*64+bh)*4096 + q*64;
        s0 += p[lane]; s1 += p[lane+32];
    }
    s0 *= scale; s1 *= scale;
    float mx = fmaxf(s0, s1);
    for (int o = 16; o; o >>= 1) mx = fmaxf(mx, __shfl_xor_sync(~0u, mx, o));
    float e0 = __expf(s0-mx), e1 = __expf(s1-mx);
    float sum = e0+e1;
    for (int o = 16; o; o >>= 1) sum += __shfl_xor_sync(~0u, sum, o);
    float inv = 1.f/sum;
    g_P[bh*4096 + q*64 + lane]    = __float2half_rn(e0*inv);
    g_P[bh*4096 + q*64 + lane+32] = __float2half_rn(e1*inv);
}

// ---------- PV ----------
__global__ __launch_bounds__(256) void attn_pv_kernel(){
    extern __shared__ __half smh[];
    __half* Ps = smh;            // [64][72]
    __half* Vs = smh + 4608;     // [256e][72 keys]
    u32* Psw = (u32*)Ps; u32* Vsw = (u32*)Vs;
    const int bh = blockIdx.x>>5, ec = blockIdx.x&31, e0 = ec*256;
    const int tid = threadIdx.x, w = tid>>5, gid = (tid&31)>>2, tig = tid&3;
    const u32* Pg = (const u32*)g_P + bh*2048;
    for (int i = tid; i < 2048; i += 256){
        int q = i>>5, kw = i&31;
        Psw[q*36+kw] = Pg[q*32 + kw];
    }
    const u32* Vg = (const u32*)g_vh + (u64)bh*64*4096;
    for (int i = tid; i < 8192; i += 256){
        int key = i>>7, ew = i&127;
        u32 v2 = Vg[key*4096 + (e0>>1) + ew];
        __half2 h = *(__half2*)&v2;
        Vs[(2*ew)*72 + key]   = __low2half(h);
        Vs[(2*ew+1)*72 + key] = __high2half(h);
    }
    __syncthreads();
    const int mw = w&3, eh = w>>2;
    float acc[16][4] = {};
    #pragma unroll
    for (int kc = 0; kc < 4; kc++){
        const int kb = kc*8 + tig;
        int qr = mw*16 + gid;
        u32 a0 = Psw[qr*36 + kb],     a1 = Psw[(qr+8)*36 + kb];
        u32 a2 = Psw[qr*36 + kb + 4], a3 = Psw[(qr+8)*36 + kb + 4];
        #pragma unroll
        for (int nt = 0; nt < 16; nt++){
            int e = eh*128 + nt*8 + gid;
            mma16(acc[nt], a0, a1, a2, a3, Vsw[e*36+kb], Vsw[e*36+kb+4]);
        }
    }
    const int b = bh>>3, h = bh&7;
    const int qA = mw*16+gid, qB = qA+8;
    const int sA = ((qA>>3)*32)*256 + (qA&7)*32;
    const int sB = ((qB>>3)*32)*256 + (qB&7)*32;
    #pragma unroll
    for (int nt = 0; nt < 16; nt++){
        int eg = e0 + eh*128 + nt*8 + tig*2;
        int d = eg>>10, py = (eg>>5)&31, px = eg&31;
        __half* base = g_yh + (u64)(b*64 + h*8 + d)*HWSZ + py*256 + px;
        *(__half2*)&base[sA] = __halves2half2(__float2half_rn(acc[nt][0]),
                                              __float2half_rn(acc[nt][1]));
        *(__half2*)&base[sB] = __halves2half2(__float2half_rn(acc[nt][2]),
                                              __float2half_rn(acc[nt][3]));
    }
}

// ---------- conv 3x3: 8x32 tile, 8 warps, ldmatrix frags, double-buffered weights ----------
template<int D>
__global__ __launch_bounds__(256, 2) void conv_mma_kernel(
        const float* __restrict__ srcf, const __half* __restrict__ srch,
        const __half* __restrict__ gw, const float* __restrict__ bias,
        const float* __restrict__ resid, float* __restrict__ dstf,
        __half* __restrict__ dsth){
    constexpr int ROWS = 8 + 2*D, COLS = 32 + 2*D, RC = ROWS*COLS;
    extern __shared__ __half smh[];
    __half* In = smh;                  // [RC pos][72 ci halves]
    __half* Wt = smh + RC*72;          // 2 x [64 oc][72 ci halves]
    u32* Wtw = (u32*)Wt;
    const int tid = threadIdx.x, w = tid>>5, lane = tid&31;
    const int gid = lane>>2, tig = lane&3;
    const int b = blockIdx.z, y0 = blockIdx.y*8, x0 = blockIdx.x*32;
    __shared__ int yoff[12], xoff[36];
    if (tid < ROWS) yoff[tid] = refl(y0 - D + tid, HH)*256;
    if (tid >= 64 && tid < 64+COLS) xoff[tid-64] = refl(x0 - D + (tid-64), WW);
    __syncthreads();
    const u32* gww = (const u32*)gw;
    for (int i = tid; i < 2304; i += 256) Wtw[i] = gww[i];   // tap0 -> buf0
    for (int i = tid; i < 64*RC; i += 256){
        int ci = i/RC, rem = i - ci*RC;
        int r = rem/COLS, c = rem - r*COLS;
        u64 gi = (u64)(b*64+ci)*HWSZ + yoff[r] + xoff[c];
        In[rem*72 + ci] = srch ? srch[gi] : __float2half_rn(srcf[gi]);
    }
    __syncthreads();

    // per-lane ldmatrix base addresses
    const u32 InB = (u32)__cvta_generic_to_shared(In);
    const u32 WtB = (u32)__cvta_generic_to_shared(Wt);
    const int g1 = (lane>>3)&1, g2 = lane>>4, rin = lane&7;
    const u32 Abase = InB + ((rin + g1*8)*72 + g2*8)*2;            // + (pos*72 + kc*16)*2
    const u32 Bbase = WtB + ((g2*8 + rin)*72 + g1*8)*2;            // + (buf*4608 + np*16*72 + kc*16)*2

    const int sx = (w>>2)*16, wr = w&3;
    float acc[2][8][4] = {};
    u32 wreg[9];
    for (int tap = 0; tap < 9; tap++){
        if (tap < 8){
            #pragma unroll
            for (int rr = 0; rr < 9; rr++)
                wreg[rr] = gww[(tap+1)*2304 + tid + rr*256];
        }
        const int dy = tap/3, dx = tap - dy*3;
        const int cb = sx + dx*D;
        const u32 Bb = Bbase + (tap&1)*9216;
        #pragma unroll
        for (int kc = 0; kc < 4; kc++){
            u32 bf[8][2];
            #pragma unroll
            for (int np = 0; np < 4; np++)
                ldsm4(bf[2*np][0], bf[2*np][1], bf[2*np+1][0], bf[2*np+1][1],
                      Bb + (np*1152 + kc*16)*2);
            #pragma unroll
            for (int mt = 0; mt < 2; mt++){
                int pos = (2*wr + mt + dy*D)*COLS + cb;
                u32 a0, a1, a2, a3;
                ldsm4(a0, a1, a2, a3, Abase + (pos*72 + kc*16)*2);
                #pragma unroll
                for (int nt = 0; nt < 8; nt++)
                    mma16(acc[mt][nt], a0, a1, a2, a3, bf[nt][0], bf[nt][1]);
            }
        }
        if (tap < 8){
            u32* dstw = Wtw + ((tap+1)&1)*2304;
            #pragma unroll
            for (int rr = 0; rr < 9; rr++)
                dstw[tid + rr*256] = wreg[rr];
            __syncthreads();
        }
    }

    float bv0[8], bv1[8];
    #pragma unroll
    for (int nt = 0; nt < 8; nt++){
        bv0[nt] = __ldg(&bias[nt*8 + tig*2]);
        bv1[nt] = __ldg(&bias[nt*8 + tig*2 + 1]);
    }
    #pragma unroll
    for (int mt = 0; mt < 2; mt++){
        const int yy = y0 + wr*2 + mt;
        const int rowbase = b*64*HWSZ + yy*256 + x0 + sx + gid;
        #pragma unroll
        for (int nt = 0; nt < 8; nt++){
            const int a00 = rowbase + (nt*8 + tig*2)*HWSZ;
            float v0 = lrelu(acc[mt][nt][0] + bv0[nt]);
            float v1 = lrelu(acc[mt][nt][1] + bv1[nt]);
            float v2 = lrelu(acc[mt][nt][2] + bv0[nt]);
            float v3 = lrelu(acc[mt][nt][3] + bv1[nt]);
            if (resid){
                v0 += resid[a00];
                v1 += resid[a00 + HWSZ];
                v2 += resid[a00 + 8];
                v3 += resid[a00 + HWSZ + 8];
            }
            if (dstf){
                dstf[a00]            = v0;
                dstf[a00 + HWSZ]     = v1;
                dstf[a00 + 8]        = v2;
                dstf[a00 + HWSZ + 8] = v3;
            }
            if (dsth){
                dsth[a00]            = __float2half_rn(v0);
                dsth[a00 + HWSZ]     = __float2half_rn(v1);
                dsth[a00 + 8]        = __float2half_rn(v2);
                dsth[a00 + HWSZ + 8] = __float2half_rn(v3);
            }
        }
    }
}

extern "C" void kernel_launch(void* const* d_in, const int* in_sizes, int n_in,
                              void* d_out, int out_size){
    const float* x   = (const float*)d_in[0];
    const float* wq  = (const float*)d_in[2];
    const float* bq  = (const float*)d_in[3];
    const float* wk  = (const float*)d_in[4];
    const float* bk  = (const float*)d_in[5];
    const float* wv  = (const float*)d_in[6];
    const float* bv  = (const float*)d_in[7];
    const float* wo  = (const float*)d_in[8];
    const float* bo  = (const float*)d_in[9];
    const float* wf1 = (const float*)d_in[10];
    const float* bf1 = (const float*)d_in[11];
    const float* wf2 = (const float*)d_in[12];
    const float* bf2 = (const float*)d_in[13];
    float* out = (float*)d_out;

    float *px1; __half *pyh, *px1h, *pth, *pwt;
    cudaGetSymbolAddress((void**)&px1,  g_x1);
    cudaGetSymbolAddress((void**)&px1h, g_x1h);
    cudaGetSymbolAddress((void**)&pth,  g_th);
    cudaGetSymbolAddress((void**)&pyh,  g_yh);
    cudaGetSymbolAddress((void**)&pwt,  g_wth);

    const int QKV_SMEM = (13824 + 128*72) * 2;          // 46080 B
    const int PV_SMEM  = (4608 + 256*72) * 2;           // 46080 B
    const int SM1 = 340*144 + 18432;                    // 67392 B
    const int SM2 = 432*144 + 18432;                    // 80640 B
    cudaFuncSetAttribute(qkv_kernel, cudaFuncAttributeMaxDynamicSharedMemorySize, QKV_SMEM);
    cudaFuncSetAttribute(attn_pv_kernel, cudaFuncAttributeMaxDynamicSharedMemorySize, PV_SMEM);
    cudaFuncSetAttribute(conv_mma_kernel<1>, cudaFuncAttributeMaxDynamicSharedMemorySize, SM1);
    cudaFuncSetAttribute(conv_mma_kernel<2>, cudaFuncAttributeMaxDynamicSharedMemorySize, SM2);

    dim3 cg(8, 32, BB);
    xform_kernel<<<144, 256>>>(wq, bq, wk, bk, wv, bv, wo, wf1, wf2);
    qkv_kernel<<<dim3(2, 256, BB), 256, QKV_SMEM>>>(x);
    attn_scores_kernel<<<1024, 128>>>();
    // PROBE at slot 3 (the profiled slot): new conv on x -> scratch, overwritten later
    conv_mma_kernel<1><<<cg, 256, SM1>>>(x, nullptr, pwt, bo, nullptr, px1, nullptr);
    softmax_kernel<<<512, 256>>>();
    attn_pv_kernel<<<2048, 256, PV_SMEM>>>();
    conv_mma_kernel<1><<<cg, 256, SM1>>>(nullptr, pyh,  pwt,           bo,  x,       px1,  px1h);
    conv_mma_kernel<2><<<cg, 256, SM2>>>(nullptr, px1h, pwt + 41472,   bf1, nullptr, nullptr, pth);
    conv_mma_kernel<1><<<cg, 256, SM1>>>(nullptr, pth,  pwt + 2*41472, bf2, px1,     out,  nullptr);
}

// round 15
// speedup vs baseline: 1.1206x; 1.1206x over previous
#include <cuda_runtime.h>
#include <cuda_fp16.h>
#include <math.h>
#include <stdint.h>

#define BB 8
#define HH 256
#define WW 256
#define EE 8192
#define HWSZ 65536
typedef unsigned long long u64;
typedef uint32_t u32;

__device__ __half g_qh[64*64*EE];
__device__ __half g_kh[64*64*EE];
__device__ __half g_vh[64*64*EE];
__device__ float  g_Sp[16*64*4096];
__device__ __half g_P[64*4096];
__device__ __half g_yh[BB*64*HWSZ];
__device__ float  g_x1[BB*64*HWSZ];
__device__ __half g_x1h[BB*64*HWSZ];
__device__ __half g_th[BB*64*HWSZ];
__device__ __half g_wqkvh[192*72];
__device__ float  g_bqkv[192];
__device__ __half g_wth[3*9*64*72];    // [conv][tap][oc][ci] stride 72

__device__ __forceinline__ int refl(int i, int n){
    if (i < 0) i = -i; if (i >= n) i = 2*n-2-i; return i; }
__device__ __forceinline__ float lrelu(float v){ return v > 0.f ? v : 0.2f*v; }

__device__ __forceinline__ void mma16(float* c, u32 a0, u32 a1, u32 a2, u32 a3,
                                      u32 b0, u32 b1){
    asm("mma.sync.aligned.m16n8k16.row.col.f32.f16.f16.f32 "
        "{%0,%1,%2,%3},{%4,%5,%6,%7},{%8,%9},{%0,%1,%2,%3};"
        : "+f"(c[0]),"+f"(c[1]),"+f"(c[2]),"+f"(c[3])
        : "r"(a0),"r"(a1),"r"(a2),"r"(a3),"r"(b0),"r"(b1));
}
__device__ __forceinline__ void ldsm4(u32& r0, u32& r1, u32& r2, u32& r3, u32 addr){
    asm volatile("ldmatrix.sync.aligned.m8n8.x4.shared.b16 {%0,%1,%2,%3}, [%4];"
        : "=r"(r0),"=r"(r1),"=r"(r2),"=r"(r3) : "r"(addr));
}
__device__ __forceinline__ void cpa4(u32 smem, const void* g){
    asm volatile("cp.async.ca.shared.global [%0], [%1], 4;" :: "r"(smem), "l"(g));
}
#define CPA_COMMIT() asm volatile("cp.async.commit_group;" ::: "memory")
#define CPA_WAIT0()  asm volatile("cp.async.wait_group 0;" ::: "memory")

// ---------- weight transform ----------
__global__ void xform_kernel(const float* __restrict__ wq, const float* __restrict__ bq,
                             const float* __restrict__ wk, const float* __restrict__ bk,
                             const float* __restrict__ wv, const float* __restrict__ bv,
                             const float* __restrict__ wo, const float* __restrict__ wf1,
                             const float* __restrict__ wf2){
    int idx = blockIdx.x*256 + threadIdx.x;
    if (idx < 12288){
        int oc = idx>>6, ci = idx&63;
        int t3 = oc>>6, r = (oc&63)*64 + ci;
        float v = (t3==0) ? wq[r] : (t3==1 ? wk[r] : wv[r]);
        g_wqkvh[oc*72 + ci] = __float2half_rn(v);
    }
    if (idx < 192)
        g_bqkv[idx] = (idx<64) ? bq[idx] : (idx<128 ? bk[idx-64] : bv[idx-128]);
    if (idx < 36864){
        int tap = idx>>12, oc = (idx&4095)>>6, ci = idx&63;
        int s = (oc*64+ci)*9 + tap;
        int d = (tap*64 + oc)*72 + ci;
        g_wth[d]            = __float2half_rn(wo[s]);
        g_wth[41472 + d]    = __float2half_rn(wf1[s]);
        g_wth[2*41472 + d]  = __float2half_rn(wf2[s]);
    }
}

// ---------- qkv 1x1 conv: 512 thr, 16 warps = 4 mg x 4 nb; acc 48 regs ----------
__global__ __launch_bounds__(512) void qkv_kernel(const float* __restrict__ x){
    extern __shared__ __half smh[];
    __half* Ws = smh;            // [192][72]
    __half* Xn = smh + 13824;    // [128px][72]
    u32* Wsw = (u32*)Ws; u32* Xnw = (u32*)Xn;
    const int tid = threadIdx.x, w = tid>>5, gid = (tid&31)>>2, tig = tid&3;
    const int b = blockIdx.z, y = blockIdx.y, x0 = blockIdx.x*128;
    const u32* gww = (const u32*)g_wqkvh;
    for (int i = tid; i < 6912; i += 512) Wsw[i] = gww[i];
    for (int i = tid; i < 8192; i += 512){
        int ci = i>>7, px = i&127;
        Xn[px*72 + ci] = __float2half_rn(x[(b*64+ci)*HWSZ + y*256 + x0 + px]);
    }
    __syncthreads();
    const int mg = (w&3)*3, nb = (w>>2)*32;
    float acc[3][4][4] = {};
    #pragma unroll
    for (int kc = 0; kc < 4; kc++){
        const int kb = kc*8 + tig;
        u32 bf0[4], bf1[4];
        #pragma unroll
        for (int nt = 0; nt < 4; nt++){
            int px = nb + nt*8 + gid;
            bf0[nt] = Xnw[px*36 + kb];
            bf1[nt] = Xnw[px*36 + kb + 4];
        }
        #pragma unroll
        for (int mt = 0; mt < 3; mt++){
            int oc = (mg+mt)*16 + gid;
            u32 a0 = Wsw[oc*36 + kb],       a1 = Wsw[(oc+8)*36 + kb];
            u32 a2 = Wsw[oc*36 + kb + 4],   a3 = Wsw[(oc+8)*36 + kb + 4];
            #pragma unroll
            for (int nt = 0; nt < 4; nt++)
                mma16(acc[mt][nt], a0, a1, a2, a3, bf0[nt], bf1[nt]);
        }
    }
    const int pyo = (y&31)*32, wrow = (y>>5)*8;
    #pragma unroll
    for (int mt = 0; mt < 3; mt++){
        int ocA = (mg+mt)*16 + gid, ocB = ocA + 8;
        float bA = g_bqkv[ocA], bB = g_bqkv[ocB];
        int t3A = ocA>>6, cA = ocA&63;
        int t3B = ocB>>6, cB = ocB&63;
        __half* pA = (t3A==0?g_qh:(t3A==1?g_kh:g_vh)) + (u64)(b*8+(cA>>3))*64*EE + (cA&7)*1024;
        __half* pB = (t3B==0?g_qh:(t3B==1?g_kh:g_vh)) + (u64)(b*8+(cB>>3))*64*EE + (cB&7)*1024;
        #pragma unroll
        for (int nt = 0; nt < 4; nt++){
            int px = x0 + nb + nt*8 + tig*2;
            int wo2 = (wrow + (px>>5))*EE + pyo + (px&31);
            *(__half2*)&pA[wo2] = __halves2half2(__float2half_rn(acc[mt][nt][0]+bA),
                                                 __float2half_rn(acc[mt][nt][1]+bA));
            *(__half2*)&pB[wo2] = __halves2half2(__float2half_rn(acc[mt][nt][2]+bB),
                                                 __float2half_rn(acc[mt][nt][3]+bB));
        }
    }
}

// ---------- scores ----------
__global__ __launch_bounds__(128) void attn_scores_kernel(){
    __shared__ __half Qs[64*72];
    __shared__ __half Ks[64*72];
    u32* Qsw = (u32*)Qs; u32* Ksw = (u32*)Ks;
    const int bh = blockIdx.x>>4, sl = blockIdx.x&15, e0 = sl*512;
    const int tid = threadIdx.x, w = tid>>5, gid = (tid&31)>>2, tig = tid&3;
    const u32* Qg = (const u32*)g_qh + (u64)bh*64*4096;
    const u32* Kg = (const u32*)g_kh + (u64)bh*64*4096;
    float acc[8][4] = {};
    for (int ec = 0; ec < 8; ec++){
        __syncthreads();
        const int eoff = (e0 + ec*64)>>1;
        for (int i = tid; i < 2048; i += 128){
            int q = i>>5, ew = i&31;
            Qsw[q*36+ew] = Qg[q*4096 + eoff + ew];
            Ksw[q*36+ew] = Kg[q*4096 + eoff + ew];
        }
        __syncthreads();
        #pragma unroll
        for (int kc = 0; kc < 4; kc++){
            const int kb = kc*8 + tig;
            int qr = w*16 + gid;
            u32 a0 = Qsw[qr*36 + kb],     a1 = Qsw[(qr+8)*36 + kb];
            u32 a2 = Qsw[qr*36 + kb + 4], a3 = Qsw[(qr+8)*36 + kb + 4];
            #pragma unroll
            for (int nt = 0; nt < 8; nt++){
                int key = nt*8 + gid;
                mma16(acc[nt], a0, a1, a2, a3, Ksw[key*36+kb], Ksw[key*36+kb+4]);
            }
        }
    }
    float* Sp = g_Sp + (u64)(sl*64+bh)*4096;
    int qA = w*16+gid, qB = qA+8;
    #pragma unroll
    for (int nt = 0; nt < 8; nt++){
        int key = nt*8 + tig*2;
        *(float2*)&Sp[qA*64+key] = make_float2(acc[nt][0], acc[nt][1]);
        *(float2*)&Sp[qB*64+key] = make_float2(acc[nt][2], acc[nt][3]);
    }
}

// ---------- softmax ----------
__global__ void softmax_kernel(){
    const int r = blockIdx.x*8 + (threadIdx.x>>5);
    const int bh = r>>6, q = r&63, lane = threadIdx.x&31;
    const float scale = 0.011048543456039806f;
    float s0 = 0.f, s1 = 0.f;
    #pragma unroll
    for (int sl = 0; sl < 16; sl++){
        const float* p = g_Sp + (u64)(sl*64+bh)*4096 + q*64;
        s0 += p[lane]; s1 += p[lane+32];
    }
    s0 *= scale; s1 *= scale;
    float mx = fmaxf(s0, s1);
    for (int o = 16; o; o >>= 1) mx = fmaxf(mx, __shfl_xor_sync(~0u, mx, o));
    float e0 = __expf(s0-mx), e1 = __expf(s1-mx);
    float sum = e0+e1;
    for (int o = 16; o; o >>= 1) sum += __shfl_xor_sync(~0u, sum, o);
    float inv = 1.f/sum;
    g_P[bh*4096 + q*64 + lane]    = __float2half_rn(e0*inv);
    g_P[bh*4096 + q*64 + lane+32] = __float2half_rn(e1*inv);
}

// ---------- PV ----------
__global__ __launch_bounds__(256) void attn_pv_kernel(){
    extern __shared__ __half smh[];
    __half* Ps = smh;            // [64][72]
    __half* Vs = smh + 4608;     // [256e][72 keys]
    u32* Psw = (u32*)Ps; u32* Vsw = (u32*)Vs;
    const int bh = blockIdx.x>>5, ec = blockIdx.x&31, e0 = ec*256;
    const int tid = threadIdx.x, w = tid>>5, gid = (tid&31)>>2, tig = tid&3;
    const u32* Pg = (const u32*)g_P + bh*2048;
    for (int i = tid; i < 2048; i += 256){
        int q = i>>5, kw = i&31;
        Psw[q*36+kw] = Pg[q*32 + kw];
    }
    const u32* Vg = (const u32*)g_vh + (u64)bh*64*4096;
    for (int i = tid; i < 8192; i += 256){
        int key = i>>7, ew = i&127;
        u32 v2 = Vg[key*4096 + (e0>>1) + ew];
        __half2 h = *(__half2*)&v2;
        Vs[(2*ew)*72 + key]   = __low2half(h);
        Vs[(2*ew+1)*72 + key] = __high2half(h);
    }
    __syncthreads();
    const int mw = w&3, eh = w>>2;
    float acc[16][4] = {};
    #pragma unroll
    for (int kc = 0; kc < 4; kc++){
        const int kb = kc*8 + tig;
        int qr = mw*16 + gid;
        u32 a0 = Psw[qr*36 + kb],     a1 = Psw[(qr+8)*36 + kb];
        u32 a2 = Psw[qr*36 + kb + 4], a3 = Psw[(qr+8)*36 + kb + 4];
        #pragma unroll
        for (int nt = 0; nt < 16; nt++){
            int e = eh*128 + nt*8 + gid;
            mma16(acc[nt], a0, a1, a2, a3, Vsw[e*36+kb], Vsw[e*36+kb+4]);
        }
    }
    const int b = bh>>3, h = bh&7;
    const int qA = mw*16+gid, qB = qA+8;
    const int sA = ((qA>>3)*32)*256 + (qA&7)*32;
    const int sB = ((qB>>3)*32)*256 + (qB&7)*32;
    #pragma unroll
    for (int nt = 0; nt < 16; nt++){
        int eg = e0 + eh*128 + nt*8 + tig*2;
        int d = eg>>10, py = (eg>>5)&31, px = eg&31;
        __half* base = g_yh + (u64)(b*64 + h*8 + d)*HWSZ + py*256 + px;
        *(__half2*)&base[sA] = __halves2half2(__float2half_rn(acc[nt][0]),
                                              __float2half_rn(acc[nt][1]));
        *(__half2*)&base[sB] = __halves2half2(__float2half_rn(acc[nt][2]),
                                              __float2half_rn(acc[nt][3]));
    }
}

// ---------- conv 3x3: 8x16 tile, 8 warps (m16 each), cp.async weights, 32-reg acc ----------
template<int D>
__global__ __launch_bounds__(256, 3) void conv_mma_kernel(
        const float* __restrict__ srcf, const __half* __restrict__ srch,
        const __half* __restrict__ gw, const float* __restrict__ bias,
        const float* __restrict__ resid, float* __restrict__ dstf,
        __half* __restrict__ dsth){
    constexpr int ROWS = 8 + 2*D, COLS = 16 + 2*D, RC = ROWS*COLS;
    extern __shared__ __half smh[];
    __half* In = smh;                  // [RC][72]
    __half* Wt = smh + RC*72;          // 2 x [64][72]
    const int tid = threadIdx.x, w = tid>>5, lane = tid&31;
    const int gid = lane>>2, tig = lane&3;
    const int b = blockIdx.z, y0 = blockIdx.y*8, x0 = blockIdx.x*16;
    __shared__ int yoff[12], xoff[20];
    if (tid < ROWS) yoff[tid] = refl(y0 - D + tid, HH)*256;
    if (tid >= 32 && tid < 32+COLS) xoff[tid-32] = refl(x0 - D + (tid-32), WW);
    const u32 InB = (u32)__cvta_generic_to_shared(In);
    const u32 WtB = (u32)__cvta_generic_to_shared(Wt);
    const u32* gww = (const u32*)gw;
    // G0: tap0 weights -> buf0
    #pragma unroll
    for (int rr = 0; rr < 9; rr++)
        cpa4(WtB + (tid + rr*256)*4, gww + tid + rr*256);
    CPA_COMMIT();
    __syncthreads();          // yoff/xoff ready
    for (int i = tid; i < 64*RC; i += 256){
        int ci = i/RC, rem = i - ci*RC;
        int r = rem/COLS, c = rem - r*COLS;
        u64 gi = (u64)(b*64+ci)*HWSZ + yoff[r] + xoff[c];
        In[rem*72 + ci] = srch ? srch[gi] : __float2half_rn(srcf[gi]);
    }

    const int g1 = (lane>>3)&1, g2 = lane>>4, rin = lane&7;
    const u32 Bbase = WtB + ((g2*8 + rin)*72 + g1*8)*2;
    float acc[8][4] = {};
    for (int tap = 0; tap < 9; tap++){
        CPA_WAIT0();          // weights for this tap have landed
        __syncthreads();      // ..in every warp's view; prev buf free; In ready (tap0)
        if (tap < 8){
            const u32* s = gww + (tap+1)*2304;
            const u32 dbase = WtB + ((tap+1)&1)*9216;
            #pragma unroll
            for (int rr = 0; rr < 9; rr++)
                cpa4(dbase + (tid + rr*256)*4, s + tid + rr*256);
            CPA_COMMIT();
        }
        const int dy = tap/3, dx = tap - dy*3;
        const u32 Ab = InB + (((w + dy*D)*COLS + dx*D + rin + g1*8)*72 + g2*8)*2;
        const u32 Bb = Bbase + (tap&1)*9216;
        #pragma unroll
        for (int kc = 0; kc < 4; kc++){
            u32 a0, a1, a2, a3;
            ldsm4(a0, a1, a2, a3, Ab + kc*32);
            u32 bf[8][2];
            #pragma unroll
            for (int np = 0; np < 4; np++)
                ldsm4(bf[2*np][0], bf[2*np][1], bf[2*np+1][0], bf[2*np+1][1],
                      Bb + (np*1152 + kc*16)*2);
            #pragma unroll
            for (int nt = 0; nt < 8; nt++)
                mma16(acc[nt], a0, a1, a2, a3, bf[nt][0], bf[nt][1]);
        }
    }

    float bv0[8], bv1[8];
    #pragma unroll
    for (int nt = 0; nt < 8; nt++){
        bv0[nt] = __ldg(&bias[nt*8 + tig*2]);
        bv1[nt] = __ldg(&bias[nt*8 + tig*2 + 1]);
    }
    const int yy = y0 + w;
    const int rowbase = b*64*HWSZ + yy*256 + x0 + gid;
    #pragma unroll
    for (int nt = 0; nt < 8; nt++){
        const int a00 = rowbase + (nt*8 + tig*2)*HWSZ;
        float v0 = lrelu(acc[nt][0] + bv0[nt]);   // (x0+gid,     oc)
        float v1 = lrelu(acc[nt][1] + bv1[nt]);   // (x0+gid,     oc+1)
        float v2 = lrelu(acc[nt][2] + bv0[nt]);   // (x0+gid+8,   oc)
        float v3 = lrelu(acc[nt][3] + bv1[nt]);   // (x0+gid+8,   oc+1)
        if (resid){
            v0 += resid[a00];
            v1 += resid[a00 + HWSZ];
            v2 += resid[a00 + 8];
            v3 += resid[a00 + HWSZ + 8];
        }
        if (dstf){
            dstf[a00]            = v0;
            dstf[a00 + HWSZ]     = v1;
            dstf[a00 + 8]        = v2;
            dstf[a00 + HWSZ + 8] = v3;
        }
        if (dsth){
            dsth[a00]            = __float2half_rn(v0);
            dsth[a00 + HWSZ]     = __float2half_rn(v1);
            dsth[a00 + 8]        = __float2half_rn(v2);
            dsth[a00 + HWSZ + 8] = __float2half_rn(v3);
        }
    }
}

extern "C" void kernel_launch(void* const* d_in, const int* in_sizes, int n_in,
                              void* d_out, int out_size){
    const float* x   = (const float*)d_in[0];
    const float* wq  = (const float*)d_in[2];
    const float* bq  = (const float*)d_in[3];
    const float* wk  = (const float*)d_in[4];
    const float* bk  = (const float*)d_in[5];
    const float* wv  = (const float*)d_in[6];
    const float* bv  = (const float*)d_in[7];
    const float* wo  = (const float*)d_in[8];
    const float* bo  = (const float*)d_in[9];
    const float* wf1 = (const float*)d_in[10];
    const float* bf1 = (const float*)d_in[11];
    const float* wf2 = (const float*)d_in[12];
    const float* bf2 = (const float*)d_in[13];
    float* out = (float*)d_out;

    float *px1; __half *pyh, *px1h, *pth, *pwt;
    cudaGetSymbolAddress((void**)&px1,  g_x1);
    cudaGetSymbolAddress((void**)&px1h, g_x1h);
    cudaGetSymbolAddress((void**)&pth,  g_th);
    cudaGetSymbolAddress((void**)&pyh,  g_yh);
    cudaGetSymbolAddress((void**)&pwt,  g_wth);

    const int QKV_SMEM = (13824 + 128*72) * 2;          // 46080 B
    const int PV_SMEM  = (4608 + 256*72) * 2;           // 46080 B
    const int SM1 = (180*72 + 2*64*72) * 2;             // 44352 B
    const int SM2 = (240*72 + 2*64*72) * 2;             // 52992 B
    cudaFuncSetAttribute(qkv_kernel, cudaFuncAttributeMaxDynamicSharedMemorySize, QKV_SMEM);
    cudaFuncSetAttribute(attn_pv_kernel, cudaFuncAttributeMaxDynamicSharedMemorySize, PV_SMEM);
    cudaFuncSetAttribute(conv_mma_kernel<1>, cudaFuncAttributeMaxDynamicSharedMemorySize, SM1);
    cudaFuncSetAttribute(conv_mma_kernel<2>, cudaFuncAttributeMaxDynamicSharedMemorySize, SM2);

    dim3 cg(16, 32, BB);
    xform_kernel<<<144, 256>>>(wq, bq, wk, bk, wv, bv, wo, wf1, wf2);
    qkv_kernel<<<dim3(2, 256, BB), 512, QKV_SMEM>>>(x);
    attn_scores_kernel<<<1024, 128>>>();
    // PROBE at slot 3 (the profiled slot): new conv on x -> scratch, overwritten later
    conv_mma_kernel<1><<<cg, 256, SM1>>>(x, nullptr, pwt, bo, nullptr, px1, nullptr);
    softmax_kernel<<<512, 256>>>();
    attn_pv_kernel<<<2048, 256, PV_SMEM>>>();
    conv_mma_kernel<1><<<cg, 256, SM1>>>(nullptr, pyh,  pwt,           bo,  x,       px1,  px1h);
    conv_mma_kernel<2><<<cg, 256, SM2>>>(nullptr, px1h, pwt + 41472,   bf1, nullptr, nullptr, pth);
    conv_mma_kernel<1><<<cg, 256, SM1>>>(nullptr, pth,  pwt + 2*41472, bf2, px1,     out,  nullptr);
}

// round 17
// speedup vs baseline: 1.3099x; 1.1690x over previous
#include <cuda_runtime.h>
#include <cuda_fp16.h>
#include <math.h>
#include <stdint.h>

#define BB 8
#define HH 256
#define WW 256
#define EE 8192
#define HWSZ 65536
typedef unsigned long long u64;
typedef uint32_t u32;

__device__ __half g_qh[64*64*EE];
__device__ __half g_kh[64*64*EE];
__device__ __half g_vh[64*64*EE];
__device__ float  g_Sp[16*64*4096];
__device__ __half g_P[64*4096];
__device__ __half g_yh[BB*64*HWSZ];
__device__ float  g_x1[BB*64*HWSZ];
__device__ __half g_x1h[BB*64*HWSZ];
__device__ __half g_th[BB*64*HWSZ];
__device__ __half g_wqkvh[192*72];
__device__ float  g_bqkv[192];
__device__ __half g_wth[3*36864];   // conv wt: [conv][tap][oc][64ci compact, grp^(oc&7) swizzle]

__device__ __forceinline__ int refl(int i, int n){
    if (i < 0) i = -i; if (i >= n) i = 2*n-2-i; return i; }
__device__ __forceinline__ float lrelu(float v){ return v > 0.f ? v : 0.2f*v; }

__device__ __forceinline__ void mma16(float* c, u32 a0, u32 a1, u32 a2, u32 a3,
                                      u32 b0, u32 b1){
    asm("mma.sync.aligned.m16n8k16.row.col.f32.f16.f16.f32 "
        "{%0,%1,%2,%3},{%4,%5,%6,%7},{%8,%9},{%0,%1,%2,%3};"
        : "+f"(c[0]),"+f"(c[1]),"+f"(c[2]),"+f"(c[3])
        : "r"(a0),"r"(a1),"r"(a2),"r"(a3),"r"(b0),"r"(b1));
}
__device__ __forceinline__ void ldsm4(u32& r0, u32& r1, u32& r2, u32& r3, u32 addr){
    asm volatile("ldmatrix.sync.aligned.m8n8.x4.shared.b16 {%0,%1,%2,%3}, [%4];"
        : "=r"(r0),"=r"(r1),"=r"(r2),"=r"(r3) : "r"(addr));
}

// ---------- weight transform ----------
__global__ void xform_kernel(const float* __restrict__ wq, const float* __restrict__ bq,
                             const float* __restrict__ wk, const float* __restrict__ bk,
                             const float* __restrict__ wv, const float* __restrict__ bv,
                             const float* __restrict__ wo, const float* __restrict__ wf1,
                             const float* __restrict__ wf2){
    int idx = blockIdx.x*256 + threadIdx.x;
    if (idx < 12288){
        int oc = idx>>6, ci = idx&63;
        int t3 = oc>>6, r = (oc&63)*64 + ci;
        float v = (t3==0) ? wq[r] : (t3==1 ? wk[r] : wv[r]);
        g_wqkvh[oc*72 + ci] = __float2half_rn(v);
    }
    if (idx < 192)
        g_bqkv[idx] = (idx<64) ? bq[idx] : (idx<128 ? bk[idx-64] : bv[idx-128]);
    if (idx < 36864){
        int tap = idx>>12, oc = (idx&4095)>>6, ci = idx&63;
        int s = (oc*64+ci)*9 + tap;
        // compact stride-64 with 16B-group swizzle: grp = (ci>>3) ^ (oc&7)
        int d = (tap*64 + oc)*64 + (((ci>>3) ^ (oc&7))<<3) + (ci&7);
        g_wth[d]            = __float2half_rn(wo[s]);
        g_wth[36864 + d]    = __float2half_rn(wf1[s]);
        g_wth[2*36864 + d]  = __float2half_rn(wf2[s]);
    }
}

// ---------- qkv 1x1 conv: 512 thr, 16 warps = 4 mg x 4 nb ----------
__global__ __launch_bounds__(512) void qkv_kernel(const float* __restrict__ x){
    extern __shared__ __half smh[];
    __half* Ws = smh;            // [192][72]
    __half* Xn = smh + 13824;    // [128px][72]
    u32* Wsw = (u32*)Ws; u32* Xnw = (u32*)Xn;
    const int tid = threadIdx.x, w = tid>>5, gid = (tid&31)>>2, tig = tid&3;
    const int b = blockIdx.z, y = blockIdx.y, x0 = blockIdx.x*128;
    const u32* gww = (const u32*)g_wqkvh;
    for (int i = tid; i < 6912; i += 512) Wsw[i] = gww[i];
    for (int i = tid; i < 8192; i += 512){
        int ci = i>>7, px = i&127;
        Xn[px*72 + ci] = __float2half_rn(x[(b*64+ci)*HWSZ + y*256 + x0 + px]);
    }
    __syncthreads();
    const int mg = (w&3)*3, nb = (w>>2)*32;
    float acc[3][4][4] = {};
    #pragma unroll
    for (int kc = 0; kc < 4; kc++){
        const int kb = kc*8 + tig;
        u32 bf0[4], bf1[4];
        #pragma unroll
        for (int nt = 0; nt < 4; nt++){
            int px = nb + nt*8 + gid;
            bf0[nt] = Xnw[px*36 + kb];
            bf1[nt] = Xnw[px*36 + kb + 4];
        }
        #pragma unroll
        for (int mt = 0; mt < 3; mt++){
            int oc = (mg+mt)*16 + gid;
            u32 a0 = Wsw[oc*36 + kb],       a1 = Wsw[(oc+8)*36 + kb];
            u32 a2 = Wsw[oc*36 + kb + 4],   a3 = Wsw[(oc+8)*36 + kb + 4];
            #pragma unroll
            for (int nt = 0; nt < 4; nt++)
                mma16(acc[mt][nt], a0, a1, a2, a3, bf0[nt], bf1[nt]);
        }
    }
    const int pyo = (y&31)*32, wrow = (y>>5)*8;
    #pragma unroll
    for (int mt = 0; mt < 3; mt++){
        int ocA = (mg+mt)*16 + gid, ocB = ocA + 8;
        float bA = g_bqkv[ocA], bB = g_bqkv[ocB];
        int t3A = ocA>>6, cA = ocA&63;
        int t3B = ocB>>6, cB = ocB&63;
        __half* pA = (t3A==0?g_qh:(t3A==1?g_kh:g_vh)) + (u64)(b*8+(cA>>3))*64*EE + (cA&7)*1024;
        __half* pB = (t3B==0?g_qh:(t3B==1?g_kh:g_vh)) + (u64)(b*8+(cB>>3))*64*EE + (cB&7)*1024;
        #pragma unroll
        for (int nt = 0; nt < 4; nt++){
            int px = x0 + nb + nt*8 + tig*2;
            int wo2 = (wrow + (px>>5))*EE + pyo + (px&31);
            *(__half2*)&pA[wo2] = __halves2half2(__float2half_rn(acc[mt][nt][0]+bA),
                                                 __float2half_rn(acc[mt][nt][1]+bA));
            *(__half2*)&pB[wo2] = __halves2half2(__float2half_rn(acc[mt][nt][2]+bB),
                                                 __float2half_rn(acc[mt][nt][3]+bB));
        }
    }
}

// ---------- scores ----------
__global__ __launch_bounds__(128) void attn_scores_kernel(){
    __shared__ __half Qs[64*72];
    __shared__ __half Ks[64*72];
    u32* Qsw = (u32*)Qs; u32* Ksw = (u32*)Ks;
    const int bh = blockIdx.x>>4, sl = blockIdx.x&15, e0 = sl*512;
    const int tid = threadIdx.x, w = tid>>5, gid = (tid&31)>>2, tig = tid&3;
    const u32* Qg = (const u32*)g_qh + (u64)bh*64*4096;
    const u32* Kg = (const u32*)g_kh + (u64)bh*64*4096;
    float acc[8][4] = {};
    for (int ec = 0; ec < 8; ec++){
        __syncthreads();
        const int eoff = (e0 + ec*64)>>1;
        for (int i = tid; i < 2048; i += 128){
            int q = i>>5, ew = i&31;
            Qsw[q*36+ew] = Qg[q*4096 + eoff + ew];
            Ksw[q*36+ew] = Kg[q*4096 + eoff + ew];
        }
        __syncthreads();
        #pragma unroll
        for (int kc = 0; kc < 4; kc++){
            const int kb = kc*8 + tig;
            int qr = w*16 + gid;
            u32 a0 = Qsw[qr*36 + kb],     a1 = Qsw[(qr+8)*36 + kb];
            u32 a2 = Qsw[qr*36 + kb + 4], a3 = Qsw[(qr+8)*36 + kb + 4];
            #pragma unroll
            for (int nt = 0; nt < 8; nt++){
                int key = nt*8 + gid;
                mma16(acc[nt], a0, a1, a2, a3, Ksw[key*36+kb], Ksw[key*36+kb+4]);
            }
        }
    }
    float* Sp = g_Sp + (u64)(sl*64+bh)*4096;
    int qA = w*16+gid, qB = qA+8;
    #pragma unroll
    for (int nt = 0; nt < 8; nt++){
        int key = nt*8 + tig*2;
        *(float2*)&Sp[qA*64+key] = make_float2(acc[nt][0], acc[nt][1]);
        *(float2*)&Sp[qB*64+key] = make_float2(acc[nt][2], acc[nt][3]);
    }
}

// ---------- softmax ----------
__global__ void softmax_kernel(){
    const int r = blockIdx.x*8 + (threadIdx.x>>5);
    const int bh = r>>6, q = r&63, lane = threadIdx.x&31;
    const float scale = 0.011048543456039806f;
    float s0 = 0.f, s1 = 0.f;
    #pragma unroll
    for (int sl = 0; sl < 16; sl++){
        const float* p = g_Sp + (u64)(sl*64+bh)*4096 + q*64;
        s0 += p[lane]; s1 += p[lane+32];
    }
    s0 *= scale; s1 *= scale;
    float mx = fmaxf(s0, s1);
    for (int o = 16; o; o >>= 1) mx = fmaxf(mx, __shfl_xor_sync(~0u, mx, o));
    float e0 = __expf(s0-mx), e1 = __expf(s1-mx);
    float sum = e0+e1;
    for (int o = 16; o; o >>= 1) sum += __shfl_xor_sync(~0u, sum, o);
    float inv = 1.f/sum;
    g_P[bh*4096 + q*64 + lane]    = __float2half_rn(e0*inv);
    g_P[bh*4096 + q*64 + lane+32] = __float2half_rn(e1*inv);
}

// ---------- PV ----------
__global__ __launch_bounds__(256) void attn_pv_kernel(){
    extern __shared__ __half smh[];
    __half* Ps = smh;            // [64][72]
    __half* Vs = smh + 4608;     // [256e][72 keys]
    u32* Psw = (u32*)Ps; u32* Vsw = (u32*)Vs;
    const int bh = blockIdx.x>>5, ec = blockIdx.x&31, e0 = ec*256;
    const int tid = threadIdx.x, w = tid>>5, gid = (tid&31)>>2, tig = tid&3;
    const u32* Pg = (const u32*)g_P + bh*2048;
    for (int i = tid; i < 2048; i += 256){
        int q = i>>5, kw = i&31;
        Psw[q*36+kw] = Pg[q*32 + kw];
    }
    const u32* Vg = (const u32*)g_vh + (u64)bh*64*4096;
    for (int i = tid; i < 8192; i += 256){
        int key = i>>7, ew = i&127;
        u32 v2 = Vg[key*4096 + (e0>>1) + ew];
        __half2 h = *(__half2*)&v2;
        Vs[(2*ew)*72 + key]   = __low2half(h);
        Vs[(2*ew+1)*72 + key] = __high2half(h);
    }
    __syncthreads();
    const int mw = w&3, eh = w>>2;
    float acc[16][4] = {};
    #pragma unroll
    for (int kc = 0; kc < 4; kc++){
        const int kb = kc*8 + tig;
        int qr = mw*16 + gid;
        u32 a0 = Psw[qr*36 + kb],     a1 = Psw[(qr+8)*36 + kb];
        u32 a2 = Psw[qr*36 + kb + 4], a3 = Psw[(qr+8)*36 + kb + 4];
        #pragma unroll
        for (int nt = 0; nt < 16; nt++){
            int e = eh*128 + nt*8 + gid;
            mma16(acc[nt], a0, a1, a2, a3, Vsw[e*36+kb], Vsw[e*36+kb+4]);
        }
    }
    const int b = bh>>3, h = bh&7;
    const int qA = mw*16+gid, qB = qA+8;
    const int sA = ((qA>>3)*32)*256 + (qA&7)*32;
    const int sB = ((qB>>3)*32)*256 + (qB&7)*32;
    #pragma unroll
    for (int nt = 0; nt < 16; nt++){
        int eg = e0 + eh*128 + nt*8 + tig*2;
        int d = eg>>10, py = (eg>>5)&31, px = eg&31;
        __half* base = g_yh + (u64)(b*64 + h*8 + d)*HWSZ + py*256 + px;
        *(__half2*)&base[sA] = __halves2half2(__float2half_rn(acc[nt][0]),
                                              __float2half_rn(acc[nt][1]));
        *(__half2*)&base[sB] = __halves2half2(__float2half_rn(acc[nt][2]),
                                              __float2half_rn(acc[nt][3]));
    }
}

// ---------- conv 3x3: PERSISTENT — compact swizzled weights resident, tiles looped ----------
template<int D>
__global__ __launch_bounds__(256, 2) void conv_mma_kernel(
        const float* __restrict__ srcf, const __half* __restrict__ srch,
        const __half* __restrict__ gw, const float* __restrict__ bias,
        const float* __restrict__ resid, float* __restrict__ dstf,
        __half* __restrict__ dsth){
    constexpr int ROWS = 8 + 2*D, COLS = 16 + 2*D, RC = ROWS*COLS;
    extern __shared__ __half smh[];
    __half* Wt = smh;               // [9 tap][64 oc][64 ci compact+swizzle] = 73728 B
    __half* In = smh + 36864;       // [RC][72]
    u32* Wtw = (u32*)Wt;
    const int tid = threadIdx.x, w = tid>>5, lane = tid&31;
    const int gid = lane>>2, tig = lane&3;
    const u32* gww = (const u32*)gw;
    for (int i = tid; i < 18432; i += 256) Wtw[i] = gww[i];
    float bv0[8], bv1[8];
    #pragma unroll
    for (int nt = 0; nt < 8; nt++){
        bv0[nt] = __ldg(&bias[nt*8 + tig*2]);
        bv1[nt] = __ldg(&bias[nt*8 + tig*2 + 1]);
    }
    const u32 InB = (u32)__cvta_generic_to_shared(In);
    const u32 WtB = (u32)__cvta_generic_to_shared(Wt);
    const int g1 = (lane>>3)&1, g2 = lane>>4, rin = lane&7;
    // per-lane B row base (compact stride 128B, group-swizzled by rin)
    const u32 Brow = WtB + (g2*8 + rin)*128;

    for (int t = blockIdx.x; t < 4096; t += gridDim.x){
        const int b = t>>9, y0 = ((t>>4)&31)*8, x0 = (t&15)*16;
        __syncthreads();   // all warps done reading In (1st iter: Wt staging visible)
        for (int i = tid; i < 64*RC; i += 256){
            int ci = i/RC, rem = i - ci*RC;
            int r = rem/COLS, c = rem - r*COLS;
            int yg = refl(y0 - D + r, HH), xg = refl(x0 - D + c, WW);
            u64 gi = (u64)(b*64+ci)*HWSZ + yg*256 + xg;
            In[rem*72 + ci] = srch ? srch[gi] : __float2half_rn(srcf[gi]);
        }
        __syncthreads();

        float acc[8][4] = {};
        #pragma unroll
        for (int tap = 0; tap < 9; tap++){
            const int dy = tap/3, dx = tap - dy*3;
            const u32 Ab = InB + (((w + dy*D)*COLS + dx*D + rin + g1*8)*72 + g2*8)*2;
            const u32 Bt = Brow + tap*8192;
            #pragma unroll
            for (int kc = 0; kc < 4; kc++){
                u32 a0, a1, a2, a3;
                ldsm4(a0, a1, a2, a3, Ab + kc*32);
                const u32 gsw = (u32)(((g1 + 2*kc) ^ rin)*16);
                u32 bf[8][2];
                #pragma unroll
                for (int np = 0; np < 4; np++)
                    ldsm4(bf[2*np][0], bf[2*np][1], bf[2*np+1][0], bf[2*np+1][1],
                          Bt + np*2048 + gsw);
                #pragma unroll
                for (int nt = 0; nt < 8; nt++)
                    mma16(acc[nt], a0, a1, a2, a3, bf[nt][0], bf[nt][1]);
            }
        }

        const int yy = y0 + w;
        const int rowbase = b*64*HWSZ + yy*256 + x0 + gid;
        #pragma unroll
        for (int nt = 0; nt < 8; nt++){
            const int a00 = rowbase + (nt*8 + tig*2)*HWSZ;
            float v0 = lrelu(acc[nt][0] + bv0[nt]);
            float v1 = lrelu(acc[nt][1] + bv1[nt]);
            float v2 = lrelu(acc[nt][2] + bv0[nt]);
            float v3 = lrelu(acc[nt][3] + bv1[nt]);
            if (resid){
                v0 += resid[a00];
                v1 += resid[a00 + HWSZ];
                v2 += resid[a00 + 8];
                v3 += resid[a00 + HWSZ + 8];
            }
            if (dstf){
                dstf[a00]            = v0;
                dstf[a00 + HWSZ]     = v1;
                dstf[a00 + 8]        = v2;
                dstf[a00 + HWSZ + 8] = v3;
            }
            if (dsth){
                dsth[a00]            = __float2half_rn(v0);
                dsth[a00 + HWSZ]     = __float2half_rn(v1);
                dsth[a00 + 8]        = __float2half_rn(v2);
                dsth[a00 + HWSZ + 8] = __float2half_rn(v3);
            }
        }
    }
}

extern "C" void kernel_launch(void* const* d_in, const int* in_sizes, int n_in,
                              void* d_out, int out_size){
    const float* x   = (const float*)d_in[0];
    const float* wq  = (const float*)d_in[2];
    const float* bq  = (const float*)d_in[3];
    const float* wk  = (const float*)d_in[4];
    const float* bk  = (const float*)d_in[5];
    const float* wv  = (const float*)d_in[6];
    const float* bv  = (const float*)d_in[7];
    const float* wo  = (const float*)d_in[8];
    const float* bo  = (const float*)d_in[9];
    const float* wf1 = (const float*)d_in[10];
    const float* bf1 = (const float*)d_in[11];
    const float* wf2 = (const float*)d_in[12];
    const float* bf2 = (const float*)d_in[13];
    float* out = (float*)d_out;

    float *px1; __half *pyh, *px1h, *pth, *pwt;
    cudaGetSymbolAddress((void**)&px1,  g_x1);
    cudaGetSymbolAddress((void**)&px1h, g_x1h);
    cudaGetSymbolAddress((void**)&pth,  g_th);
    cudaGetSymbolAddress((void**)&pyh,  g_yh);
    cudaGetSymbolAddress((void**)&pwt,  g_wth);

    const int QKV_SMEM = (13824 + 128*72) * 2;          // 46080 B
    const int PV_SMEM  = (4608 + 256*72) * 2;           // 46080 B
    const int SM1 = 73728 + 180*72*2;                   // 99648 B
    const int SM2 = 73728 + 240*72*2;                   // 108288 B
    cudaFuncSetAttribute(qkv_kernel, cudaFuncAttributeMaxDynamicSharedMemorySize, QKV_SMEM);
    cudaFuncSetAttribute(attn_pv_kernel, cudaFuncAttributeMaxDynamicSharedMemorySize, PV_SMEM);
    cudaFuncSetAttribute(conv_mma_kernel<1>, cudaFuncAttributeMaxDynamicSharedMemorySize, SM1);
    cudaFuncSetAttribute(conv_mma_kernel<2>, cudaFuncAttributeMaxDynamicSharedMemorySize, SM2);

    const int CG = 304;   // 2 CTAs/SM persistent
    xform_kernel<<<144, 256>>>(wq, bq, wk, bk, wv, bv, wo, wf1, wf2);
    qkv_kernel<<<dim3(2, 256, BB), 512, QKV_SMEM>>>(x);
    attn_scores_kernel<<<1024, 128>>>();
    // PROBE at slot 3 (profiled): persistent conv on x -> scratch, overwritten later
    conv_mma_kernel<1><<<CG, 256, SM1>>>(x, nullptr, pwt, bo, nullptr, px1, nullptr);
    softmax_kernel<<<512, 256>>>();
    attn_pv_kernel<<<2048, 256, PV_SMEM>>>();
    conv_mma_kernel<1><<<CG, 256, SM1>>>(nullptr, pyh,  pwt,           bo,  x,       px1,  px1h);
    conv_mma_kernel<2><<<CG, 256, SM2>>>(nullptr, px1h, pwt + 36864,   bf1, nullptr, nullptr, pth);
    conv_mma_kernel<1><<<CG, 256, SM1>>>(nullptr, pth,  pwt + 2*36864, bf2, px1,     out,  nullptr);
}